// round 9
// baseline (speedup 1.0000x reference)
#include <cuda_runtime.h>
#include <cuda_bf16.h>
#include <cstdint>

// Problem constants
#define B_   4
#define C_   256
#define H_   64
#define W_   64
#define HID  64
#define KCH  100      // s*s*k*k
#define SS   4        // s*s
#define KK   25       // k*k
#define HW   4096     // H*W
#define BN_EPS 1e-5f

// Scratch (static device allocations — allowed)
__device__ float g_h[B_ * HID * HW];        // 4 MB
__device__ float g_kern[B_ * KCH * HW];     // 6.55 MB
__device__ float g_sc[HID];
__device__ float g_sh[HID];

// ---------------------------------------------------------------------------
// Kernel 1: h[b,o,p] = sum_c w1[o,c] * x[b,c,p]
// ---------------------------------------------------------------------------
__global__ __launch_bounds__(256) void k1_gemm1(
    const float* __restrict__ x, const float* __restrict__ w1)
{
    __shared__ float4 w1s[16 * 64];
    const int b  = blockIdx.y;
    const int og = blockIdx.z;
    const int tid = threadIdx.x;

    const float4* w1g = (const float4*)(w1 + og * 16 * C_);
    for (int i = tid; i < 16 * 64; i += 256) w1s[i] = w1g[i];
    __syncthreads();

    const int p = blockIdx.x * 256 + tid;
    const float* xb = x + (size_t)b * C_ * HW + p;

    float acc[16];
#pragma unroll
    for (int o = 0; o < 16; o++) acc[o] = 0.f;

    for (int c = 0; c < C_; c += 4) {
        float xv0 = xb[(c + 0) * HW];
        float xv1 = xb[(c + 1) * HW];
        float xv2 = xb[(c + 2) * HW];
        float xv3 = xb[(c + 3) * HW];
#pragma unroll
        for (int o = 0; o < 16; o++) {
            float4 w = w1s[o * 64 + (c >> 2)];
            acc[o] += w.x * xv0 + w.y * xv1 + w.z * xv2 + w.w * xv3;
        }
    }

    float* hb = g_h + ((size_t)b * HID + og * 16) * HW + p;
#pragma unroll
    for (int o = 0; o < 16; o++) hb[o * HW] = acc[o];
}

// ---------------------------------------------------------------------------
// Kernel 2: per-channel batch-norm statistics -> scale/shift
// ---------------------------------------------------------------------------
__global__ __launch_bounds__(256) void k2_stats(
    const float* __restrict__ gamma, const float* __restrict__ beta)
{
    const int o = blockIdx.x;
    const int tid = threadIdx.x;
    float s = 0.f, s2 = 0.f;
    for (int b = 0; b < B_; b++) {
        const float* hp = g_h + ((size_t)b * HID + o) * HW;
        for (int i = tid; i < HW; i += 256) {
            float v = hp[i];
            s += v; s2 += v * v;
        }
    }
#pragma unroll
    for (int off = 16; off; off >>= 1) {
        s  += __shfl_down_sync(0xffffffffu, s,  off);
        s2 += __shfl_down_sync(0xffffffffu, s2, off);
    }
    __shared__ float rs[8], rs2[8];
    if ((tid & 31) == 0) { rs[tid >> 5] = s; rs2[tid >> 5] = s2; }
    __syncthreads();
    if (tid == 0) {
        float ts = 0.f, ts2 = 0.f;
#pragma unroll
        for (int w = 0; w < 8; w++) { ts += rs[w]; ts2 += rs2[w]; }
        const float invN = 1.f / (float)(B_ * HW);
        float mean  = ts * invN;
        float var   = ts2 * invN - mean * mean;
        float scale = gamma[o] * rsqrtf(var + BN_EPS);
        g_sc[o] = scale;
        g_sh[o] = beta[o] - mean * scale;
    }
}

// ---------------------------------------------------------------------------
// Kernel 3 (v2, grid (16,B) = 4096 pixels): BN apply + ReLU + GEMM2 +
// softmax, all 4 groups per thread; a[64] loaded once.
// ---------------------------------------------------------------------------
__global__ __launch_bounds__(256) void k3_kern(
    const float* __restrict__ w2, const float* __restrict__ b2)
{
    __shared__ float4 w2s[KCH * 16];   // 100 outputs x 64 c -> 25.6 KB
    __shared__ float b2s[KCH], scs[HID], shs[HID];
    const int b = blockIdx.y, tid = threadIdx.x;

    const float4* w2g = (const float4*)w2;
    for (int i = tid; i < KCH * 16; i += 256) w2s[i] = w2g[i];
    if (tid < KCH) b2s[tid] = b2[tid];
    if (tid < HID) { scs[tid] = g_sc[tid]; shs[tid] = g_sh[tid]; }
    __syncthreads();

    const int p = blockIdx.x * 256 + tid;
    const float* hb = g_h + (size_t)b * HID * HW + p;

    float a[HID];
#pragma unroll
    for (int c = 0; c < HID; c++)
        a[c] = fmaxf(fmaf(hb[c * HW], scs[c], shs[c]), 0.f);

    float* kb = g_kern + (size_t)b * KCH * HW + p;

#pragma unroll 1
    for (int g = 0; g < SS; g++) {
        float v[KK];
        float vmax = -1e30f;
#pragma unroll
        for (int q = 0; q < KK; q++) {
            const int o = g * KK + q;
            float acc = b2s[o];
#pragma unroll
            for (int c4 = 0; c4 < 16; c4++) {
                float4 w = w2s[o * 16 + c4];
                acc += w.x * a[4 * c4] + w.y * a[4 * c4 + 1]
                     + w.z * a[4 * c4 + 2] + w.w * a[4 * c4 + 3];
            }
            v[q] = acc;
            vmax = fmaxf(vmax, acc);
        }
        float ssum = 0.f;
#pragma unroll
        for (int q = 0; q < KK; q++) { v[q] = __expf(v[q] - vmax); ssum += v[q]; }
        float inv = 1.f / ssum;
#pragma unroll
        for (int q = 0; q < KK; q++) kb[(g * KK + q) * HW] = v[q] * inv;
    }
}

// ---------------------------------------------------------------------------
// Kernel 4 (v3): reassembly + pixel shuffle, double-buffered halo.
// Thread = (pixel, si-half): kr[50], 4 channels/step via float4 smem loads.
// Block = 128 thr, tile 16x4, halo 20x8. CSPLIT=4 -> 64 ch/block,
// grid = 4x16x16 = 1024 blocks. Ping-pong smem: one sync per phase;
// next phase's LDG prefetched into regs during compute.
// ---------------------------------------------------------------------------
#define CSPLIT 4
#define CPB    (C_ / CSPLIT)     // 64 channels per block
#define TW4 16
#define TH4 4
#define HWID 20                  // halo width
#define HHGT 8                   // halo height
#define NQ  4                    // channel-quads per phase (16 channels)
#define HSLOTS (NQ * HHGT * HWID)  // 640 float4 slots
#define NPHASE (CPB / (NQ * 4))    // 4
#define LPT (HSLOTS / 128)         // 5 halo slots per thread

__global__ __launch_bounds__(128, 4) void k4_reassemble(
    const float* __restrict__ x, float* __restrict__ out)
{
    __shared__ float4 xs4[2][HSLOTS];   // 2 x 10 KB

    const int bz    = blockIdx.z;
    const int b     = bz >> 2;            // CSPLIT = 4
    const int cbase = (bz & 3) * CPB;
    const int tid   = threadIdx.x;
    const int lane  = tid & 31;
    const int wrow  = tid >> 5;           // tile row 0..3
    const int pxl   = lane & 15;
    const int si    = lane >> 4;          // 0 or 1
    const int px    = blockIdx.x * TW4 + pxl;
    const int py    = blockIdx.y * TH4 + wrow;
    const int p     = py * W_ + px;

    // 50 softmax weights: groups si*2+0 and si*2+1
    float kr[50];
    {
        const float* kb = g_kern + ((size_t)b * KCH + si * 50) * HW + p;
#pragma unroll
        for (int j = 0; j < 50; j++) kr[j] = kb[j * HW];
    }

    const float* xb = x + (size_t)b * C_ * HW;
    float* ob = out + (size_t)b * C_ * (4 * HW)
              + (size_t)(2 * py + si) * (2 * W_) + 2 * px;
    const int h0 = blockIdx.y * TH4 - 2;
    const int w0 = blockIdx.x * TW4 - 2;

    // Precompute per-thread halo-load slots (fixed across phases)
    int  goff[LPT];
    bool gval[LPT];
#pragma unroll
    for (int j = 0; j < LPT; j++) {
        const int i   = tid + j * 128;
        const int q   = i / (HHGT * HWID);
        const int rem = i - q * (HHGT * HWID);
        const int r   = rem / HWID;
        const int cc  = rem - r * HWID;
        const int gh = h0 + r, gw = w0 + cc;
        gval[j] = ((unsigned)gh < (unsigned)H_) && ((unsigned)gw < (unsigned)W_);
        goff[j] = (q * 4) * HW + gh * W_ + gw;
    }

    // Load phase 0 into buffer 0
    {
        const float* base = xb + (size_t)cbase * HW;
#pragma unroll
        for (int j = 0; j < LPT; j++) {
            float4 v = make_float4(0.f, 0.f, 0.f, 0.f);
            if (gval[j]) {
                const float* xp = base + goff[j];
                v.x = xp[0]; v.y = xp[HW]; v.z = xp[2 * HW]; v.w = xp[3 * HW];
            }
            xs4[0][tid + j * 128] = v;
        }
    }
    __syncthreads();

#pragma unroll 1
    for (int phase = 0; phase < NPHASE; phase++) {
        const int cph = cbase + phase * (NQ * 4);
        const int buf = phase & 1;
        const bool has_next = (phase + 1 < NPHASE);

        // Prefetch next phase's halo into registers (front-batched LDGs)
        float4 vreg[LPT];
        if (has_next) {
            const float* base = xb + (size_t)(cph + NQ * 4) * HW;
#pragma unroll
            for (int j = 0; j < LPT; j++) {
                float4 v = make_float4(0.f, 0.f, 0.f, 0.f);
                if (gval[j]) {
                    const float* xp = base + goff[j];
                    v.x = xp[0]; v.y = xp[HW]; v.z = xp[2 * HW]; v.w = xp[3 * HW];
                }
                vreg[j] = v;
            }
        }

        // Compute from current buffer
#pragma unroll 1
        for (int q = 0; q < NQ; q++) {
            const float4* t = xs4[buf] + (q * HHGT + wrow) * HWID + pxl;
            float ax0 = 0.f, ay0 = 0.f, az0 = 0.f, aw0 = 0.f;   // sj = 0
            float ax1 = 0.f, ay1 = 0.f, az1 = 0.f, aw1 = 0.f;   // sj = 1
#pragma unroll
            for (int di = 0; di < 5; di++) {
#pragma unroll
                for (int dj = 0; dj < 5; dj++) {
                    const float4 xv = t[di * HWID + dj];
                    const float wA = kr[di * 5 + dj];
                    const float wB = kr[25 + di * 5 + dj];
                    ax0 = fmaf(wA, xv.x, ax0);  ax1 = fmaf(wB, xv.x, ax1);
                    ay0 = fmaf(wA, xv.y, ay0);  ay1 = fmaf(wB, xv.y, ay1);
                    az0 = fmaf(wA, xv.z, az0);  az1 = fmaf(wB, xv.z, az1);
                    aw0 = fmaf(wA, xv.w, aw0);  aw1 = fmaf(wB, xv.w, aw1);
                }
            }
            float* oc = ob + (size_t)(cph + q * 4) * (4 * HW);
            *(float2*)oc = make_float2(ax0, ax1);  oc += 4 * HW;
            *(float2*)oc = make_float2(ay0, ay1);  oc += 4 * HW;
            *(float2*)oc = make_float2(az0, az1);  oc += 4 * HW;
            *(float2*)oc = make_float2(aw0, aw1);
        }

        // Stage next phase into the other buffer; one sync per phase
        if (has_next) {
#pragma unroll
            for (int j = 0; j < LPT; j++)
                xs4[buf ^ 1][tid + j * 128] = vreg[j];
            __syncthreads();
        }
    }
}

// ---------------------------------------------------------------------------
extern "C" void kernel_launch(void* const* d_in, const int* in_sizes, int n_in,
                              void* d_out, int out_size)
{
    const float* x     = (const float*)d_in[0];   // [4,256,64,64]
    const float* w1    = (const float*)d_in[1];   // [64,256]
    const float* gamma = (const float*)d_in[2];   // [64]
    const float* beta  = (const float*)d_in[3];   // [64]
    const float* w2    = (const float*)d_in[4];   // [100,64]
    const float* b2    = (const float*)d_in[5];   // [100]
    float* out = (float*)d_out;                   // [4,256,128,128]

    k1_gemm1<<<dim3(16, B_, 4), 256>>>(x, w1);
    k2_stats<<<dim3(HID), 256>>>(gamma, beta);
    k3_kern<<<dim3(16, B_), 256>>>(w2, b2);
    k4_reassemble<<<dim3(W_ / TW4, H_ / TH4, B_ * CSPLIT), 128>>>(x, out);
}

// round 10
// speedup vs baseline: 1.0686x; 1.0686x over previous
#include <cuda_runtime.h>
#include <cuda_bf16.h>
#include <cstdint>

// Problem constants
#define B_   4
#define C_   256
#define H_   64
#define W_   64
#define HID  64
#define KCH  100      // s*s*k*k
#define SS   4        // s*s
#define KK   25       // k*k
#define HW   4096     // H*W
#define BN_EPS 1e-5f

// Scratch (static device allocations — allowed)
__device__ float g_h[B_ * HID * HW];        // 4 MB
__device__ float g_kern[B_ * KCH * HW];     // 6.55 MB
__device__ float g_sc[HID];
__device__ float g_sh[HID];

// ---------------------------------------------------------------------------
// Kernel 1: h[b,o,p] = sum_c w1[o,c] * x[b,c,p]
// ---------------------------------------------------------------------------
__global__ __launch_bounds__(256) void k1_gemm1(
    const float* __restrict__ x, const float* __restrict__ w1)
{
    __shared__ float4 w1s[16 * 64];
    const int b  = blockIdx.y;
    const int og = blockIdx.z;
    const int tid = threadIdx.x;

    const float4* w1g = (const float4*)(w1 + og * 16 * C_);
    for (int i = tid; i < 16 * 64; i += 256) w1s[i] = w1g[i];
    __syncthreads();

    const int p = blockIdx.x * 256 + tid;
    const float* xb = x + (size_t)b * C_ * HW + p;

    float acc[16];
#pragma unroll
    for (int o = 0; o < 16; o++) acc[o] = 0.f;

    for (int c = 0; c < C_; c += 4) {
        float xv0 = xb[(c + 0) * HW];
        float xv1 = xb[(c + 1) * HW];
        float xv2 = xb[(c + 2) * HW];
        float xv3 = xb[(c + 3) * HW];
#pragma unroll
        for (int o = 0; o < 16; o++) {
            float4 w = w1s[o * 64 + (c >> 2)];
            acc[o] += w.x * xv0 + w.y * xv1 + w.z * xv2 + w.w * xv3;
        }
    }

    float* hb = g_h + ((size_t)b * HID + og * 16) * HW + p;
#pragma unroll
    for (int o = 0; o < 16; o++) hb[o * HW] = acc[o];
}

// ---------------------------------------------------------------------------
// Kernel 2: per-channel batch-norm statistics -> scale/shift
// ---------------------------------------------------------------------------
__global__ __launch_bounds__(256) void k2_stats(
    const float* __restrict__ gamma, const float* __restrict__ beta)
{
    const int o = blockIdx.x;
    const int tid = threadIdx.x;
    float s = 0.f, s2 = 0.f;
    for (int b = 0; b < B_; b++) {
        const float* hp = g_h + ((size_t)b * HID + o) * HW;
        for (int i = tid; i < HW; i += 256) {
            float v = hp[i];
            s += v; s2 += v * v;
        }
    }
#pragma unroll
    for (int off = 16; off; off >>= 1) {
        s  += __shfl_down_sync(0xffffffffu, s,  off);
        s2 += __shfl_down_sync(0xffffffffu, s2, off);
    }
    __shared__ float rs[8], rs2[8];
    if ((tid & 31) == 0) { rs[tid >> 5] = s; rs2[tid >> 5] = s2; }
    __syncthreads();
    if (tid == 0) {
        float ts = 0.f, ts2 = 0.f;
#pragma unroll
        for (int w = 0; w < 8; w++) { ts += rs[w]; ts2 += rs2[w]; }
        const float invN = 1.f / (float)(B_ * HW);
        float mean  = ts * invN;
        float var   = ts2 * invN - mean * mean;
        float scale = gamma[o] * rsqrtf(var + BN_EPS);
        g_sc[o] = scale;
        g_sh[o] = beta[o] - mean * scale;
    }
}

// ---------------------------------------------------------------------------
// Kernel 3 (R5-proven): BN apply + ReLU + GEMM2 + softmax, per s-group.
// grid (16, B, SS) = 256 blocks, 256 thr; one 25-output group per z-slice.
// ---------------------------------------------------------------------------
__global__ __launch_bounds__(256) void k3_kern(
    const float* __restrict__ w2, const float* __restrict__ b2)
{
    __shared__ float4 w2s[KK * 16];   // 25 outputs x 64 c (as float4)
    __shared__ float b2s[KK], scs[HID], shs[HID];
    const int b = blockIdx.y, g = blockIdx.z, tid = threadIdx.x;

    const float4* w2g = (const float4*)(w2 + g * KK * HID);
    for (int i = tid; i < KK * 16; i += 256) w2s[i] = w2g[i];
    if (tid < KK)  b2s[tid] = b2[g * KK + tid];
    if (tid < HID) { scs[tid] = g_sc[tid]; shs[tid] = g_sh[tid]; }
    __syncthreads();

    const int p = blockIdx.x * 256 + tid;
    const float* hb = g_h + (size_t)b * HID * HW + p;

    float a[HID];
#pragma unroll
    for (int c = 0; c < HID; c++)
        a[c] = fmaxf(fmaf(hb[c * HW], scs[c], shs[c]), 0.f);

    float v[KK];
    float vmax = -1e30f;
#pragma unroll
    for (int q = 0; q < KK; q++) {
        float acc = b2s[q];
#pragma unroll
        for (int c4 = 0; c4 < 16; c4++) {
            float4 w = w2s[q * 16 + c4];
            acc += w.x * a[4 * c4] + w.y * a[4 * c4 + 1]
                 + w.z * a[4 * c4 + 2] + w.w * a[4 * c4 + 3];
        }
        v[q] = acc;
        vmax = fmaxf(vmax, acc);
    }
    float ssum = 0.f;
#pragma unroll
    for (int q = 0; q < KK; q++) { v[q] = __expf(v[q] - vmax); ssum += v[q]; }
    float inv = 1.f / ssum;

    float* kb = g_kern + ((size_t)b * KCH + g * KK) * HW + p;
#pragma unroll
    for (int q = 0; q < KK; q++) kb[q * HW] = v[q] * inv;
}

// ---------------------------------------------------------------------------
// Kernel 4 (v3): reassembly + pixel shuffle, double-buffered halo.
// Thread = (pixel, si-half): kr[50], 4 channels/step via float4 smem loads.
// Block = 128 thr, tile 16x4, halo 20x8. CSPLIT=4 -> 64 ch/block,
// grid = 4x16x16 = 1024 blocks. Ping-pong smem: one sync per phase;
// next phase's LDG prefetched into regs during compute.
// ---------------------------------------------------------------------------
#define CSPLIT 4
#define CPB    (C_ / CSPLIT)     // 64 channels per block
#define TW4 16
#define TH4 4
#define HWID 20                  // halo width
#define HHGT 8                   // halo height
#define NQ  4                    // channel-quads per phase (16 channels)
#define HSLOTS (NQ * HHGT * HWID)  // 640 float4 slots
#define NPHASE (CPB / (NQ * 4))    // 4
#define LPT (HSLOTS / 128)         // 5 halo slots per thread

__global__ __launch_bounds__(128, 4) void k4_reassemble(
    const float* __restrict__ x, float* __restrict__ out)
{
    __shared__ float4 xs4[2][HSLOTS];   // 2 x 10 KB

    const int bz    = blockIdx.z;
    const int b     = bz >> 2;            // CSPLIT = 4
    const int cbase = (bz & 3) * CPB;
    const int tid   = threadIdx.x;
    const int lane  = tid & 31;
    const int wrow  = tid >> 5;           // tile row 0..3
    const int pxl   = lane & 15;
    const int si    = lane >> 4;          // 0 or 1
    const int px    = blockIdx.x * TW4 + pxl;
    const int py    = blockIdx.y * TH4 + wrow;
    const int p     = py * W_ + px;

    // 50 softmax weights: groups si*2+0 and si*2+1
    float kr[50];
    {
        const float* kb = g_kern + ((size_t)b * KCH + si * 50) * HW + p;
#pragma unroll
        for (int j = 0; j < 50; j++) kr[j] = kb[j * HW];
    }

    const float* xb = x + (size_t)b * C_ * HW;
    float* ob = out + (size_t)b * C_ * (4 * HW)
              + (size_t)(2 * py + si) * (2 * W_) + 2 * px;
    const int h0 = blockIdx.y * TH4 - 2;
    const int w0 = blockIdx.x * TW4 - 2;

    // Precompute per-thread halo-load slots (fixed across phases)
    int  goff[LPT];
    bool gval[LPT];
#pragma unroll
    for (int j = 0; j < LPT; j++) {
        const int i   = tid + j * 128;
        const int q   = i / (HHGT * HWID);
        const int rem = i - q * (HHGT * HWID);
        const int r   = rem / HWID;
        const int cc  = rem - r * HWID;
        const int gh = h0 + r, gw = w0 + cc;
        gval[j] = ((unsigned)gh < (unsigned)H_) && ((unsigned)gw < (unsigned)W_);
        goff[j] = (q * 4) * HW + gh * W_ + gw;
    }

    // Load phase 0 into buffer 0
    {
        const float* base = xb + (size_t)cbase * HW;
#pragma unroll
        for (int j = 0; j < LPT; j++) {
            float4 v = make_float4(0.f, 0.f, 0.f, 0.f);
            if (gval[j]) {
                const float* xp = base + goff[j];
                v.x = xp[0]; v.y = xp[HW]; v.z = xp[2 * HW]; v.w = xp[3 * HW];
            }
            xs4[0][tid + j * 128] = v;
        }
    }
    __syncthreads();

#pragma unroll 1
    for (int phase = 0; phase < NPHASE; phase++) {
        const int cph = cbase + phase * (NQ * 4);
        const int buf = phase & 1;
        const bool has_next = (phase + 1 < NPHASE);

        // Prefetch next phase's halo into registers (front-batched LDGs)
        float4 vreg[LPT];
        if (has_next) {
            const float* base = xb + (size_t)(cph + NQ * 4) * HW;
#pragma unroll
            for (int j = 0; j < LPT; j++) {
                float4 v = make_float4(0.f, 0.f, 0.f, 0.f);
                if (gval[j]) {
                    const float* xp = base + goff[j];
                    v.x = xp[0]; v.y = xp[HW]; v.z = xp[2 * HW]; v.w = xp[3 * HW];
                }
                vreg[j] = v;
            }
        }

        // Compute from current buffer
#pragma unroll 1
        for (int q = 0; q < NQ; q++) {
            const float4* t = xs4[buf] + (q * HHGT + wrow) * HWID + pxl;
            float ax0 = 0.f, ay0 = 0.f, az0 = 0.f, aw0 = 0.f;   // sj = 0
            float ax1 = 0.f, ay1 = 0.f, az1 = 0.f, aw1 = 0.f;   // sj = 1
#pragma unroll
            for (int di = 0; di < 5; di++) {
#pragma unroll
                for (int dj = 0; dj < 5; dj++) {
                    const float4 xv = t[di * HWID + dj];
                    const float wA = kr[di * 5 + dj];
                    const float wB = kr[25 + di * 5 + dj];
                    ax0 = fmaf(wA, xv.x, ax0);  ax1 = fmaf(wB, xv.x, ax1);
                    ay0 = fmaf(wA, xv.y, ay0);  ay1 = fmaf(wB, xv.y, ay1);
                    az0 = fmaf(wA, xv.z, az0);  az1 = fmaf(wB, xv.z, az1);
                    aw0 = fmaf(wA, xv.w, aw0);  aw1 = fmaf(wB, xv.w, aw1);
                }
            }
            float* oc = ob + (size_t)(cph + q * 4) * (4 * HW);
            *(float2*)oc = make_float2(ax0, ax1);  oc += 4 * HW;
            *(float2*)oc = make_float2(ay0, ay1);  oc += 4 * HW;
            *(float2*)oc = make_float2(az0, az1);  oc += 4 * HW;
            *(float2*)oc = make_float2(aw0, aw1);
        }

        // Stage next phase into the other buffer; one sync per phase
        if (has_next) {
#pragma unroll
            for (int j = 0; j < LPT; j++)
                xs4[buf ^ 1][tid + j * 128] = vreg[j];
            __syncthreads();
        }
    }
}

// ---------------------------------------------------------------------------
extern "C" void kernel_launch(void* const* d_in, const int* in_sizes, int n_in,
                              void* d_out, int out_size)
{
    const float* x     = (const float*)d_in[0];   // [4,256,64,64]
    const float* w1    = (const float*)d_in[1];   // [64,256]
    const float* gamma = (const float*)d_in[2];   // [64]
    const float* beta  = (const float*)d_in[3];   // [64]
    const float* w2    = (const float*)d_in[4];   // [100,64]
    const float* b2    = (const float*)d_in[5];   // [100]
    float* out = (float*)d_out;                   // [4,256,128,128]

    k1_gemm1<<<dim3(16, B_, 4), 256>>>(x, w1);
    k2_stats<<<dim3(HID), 256>>>(gamma, beta);
    k3_kern<<<dim3(16, B_, SS), 256>>>(w2, b2);
    k4_reassemble<<<dim3(W_ / TW4, H_ / TH4, B_ * CSPLIT), 128>>>(x, out);
}